// round 1
// baseline (speedup 1.0000x reference)
#include <cuda_runtime.h>

// Gated DeltaNet single step, algebraically reduced:
//   out[v] = g*(q . S[:,v]) + (q . k)*beta*(v[v] - g*(k . S[:,v]))
// One CTA per (b,h); single streaming pass over state (HBM-bound, ~805 MB).

#define DK 128
#define DV 128

__global__ __launch_bounds__(DV, 8)
void deltanet_step_kernel(const float* __restrict__ q,
                          const float* __restrict__ k,
                          const float* __restrict__ v,
                          const float* __restrict__ beta,
                          const float* __restrict__ gate,
                          const float* __restrict__ state,
                          float* __restrict__ out) {
    const int bh = blockIdx.x;          // 0 .. B*H-1
    const int t  = threadIdx.x;         // 0 .. 127  (column v)

    __shared__ float sq[DK];
    __shared__ float sk[DK];

    const float* S = state + (size_t)bh * (DK * DV);

    sq[t] = q[(size_t)bh * DK + t];
    sk[t] = k[(size_t)bh * DK + t];
    __syncthreads();

    float qS = 0.0f;
    float kS = 0.0f;

    #pragma unroll 8
    for (int kk = 0; kk < DK; ++kk) {
        float s = S[(size_t)kk * DV + t];   // coalesced across threads
        qS = fmaf(sq[kk], s, qS);
        kS = fmaf(sk[kk], s, kS);
    }

    // q . k  (redundant per-thread, all from smem broadcast — negligible)
    float qk = 0.0f;
    #pragma unroll
    for (int kk = 0; kk < DK; ++kk) {
        qk = fmaf(sq[kk], sk[kk], qk);
    }

    const float g  = gate[bh];
    const float bt = beta[bh];
    const float vv = v[(size_t)bh * DV + t];

    out[(size_t)bh * DV + t] = fmaf(g, qS, qk * bt * (vv - g * kS));
}

extern "C" void kernel_launch(void* const* d_in, const int* in_sizes, int n_in,
                              void* d_out, int out_size) {
    const float* q     = (const float*)d_in[0];
    const float* k     = (const float*)d_in[1];
    const float* v     = (const float*)d_in[2];
    const float* beta  = (const float*)d_in[3];
    const float* gate  = (const float*)d_in[4];
    const float* state = (const float*)d_in[5];
    float* out = (float*)d_out;

    const int BH = in_sizes[3];   // beta has B*H elements = 256*48 = 12288

    deltanet_step_kernel<<<BH, DV>>>(q, k, v, beta, gate, state, out);
}

// round 3
// speedup vs baseline: 1.0975x; 1.0975x over previous
#include <cuda_runtime.h>

// Gated DeltaNet single step, reduced form:
//   out[v] = g*(q . S[:,v]) + (q . k)*beta*(v[v] - g*(k . S[:,v]))
// One warp per (b,h). Lane owns 4 columns via float4 (512B/row coalesced).
// HBM-bound: 805 MB single pass over state.

#define DK 128
#define DV 128
#define WARPS_PER_CTA 8

__global__ __launch_bounds__(WARPS_PER_CTA * 32)
void deltanet_step_kernel(const float* __restrict__ q,
                          const float* __restrict__ k,
                          const float* __restrict__ v,
                          const float* __restrict__ beta,
                          const float* __restrict__ gate,
                          const float* __restrict__ state,
                          float* __restrict__ out,
                          int BH) {
    const int warp = threadIdx.x >> 5;
    const int lane = threadIdx.x & 31;
    const int bh   = blockIdx.x * WARPS_PER_CTA + warp;
    if (bh >= BH) return;

    __shared__ float sq[WARPS_PER_CTA][DK];
    __shared__ float sk[WARPS_PER_CTA][DK];

    // Load this head's q,k (float4 per lane), stash in smem for broadcast.
    const float4 q4 = reinterpret_cast<const float4*>(q + (size_t)bh * DK)[lane];
    const float4 k4 = reinterpret_cast<const float4*>(k + (size_t)bh * DK)[lane];
    reinterpret_cast<float4*>(sq[warp])[lane] = q4;
    reinterpret_cast<float4*>(sk[warp])[lane] = k4;
    __syncwarp();

    // q . k from registers via butterfly reduce
    float qk = q4.x * k4.x + q4.y * k4.y + q4.z * k4.z + q4.w * k4.w;
    #pragma unroll
    for (int off = 16; off > 0; off >>= 1)
        qk += __shfl_xor_sync(0xFFFFFFFFu, qk, off);

    const float4* S = reinterpret_cast<const float4*>(state + (size_t)bh * (DK * DV));

    float4 qS = make_float4(0.f, 0.f, 0.f, 0.f);
    float4 kS = make_float4(0.f, 0.f, 0.f, 0.f);

    #pragma unroll 8
    for (int kk = 0; kk < DK; ++kk) {
        const float4 s = S[kk * (DV / 4) + lane];   // warp reads full 512B row
        const float qc = sq[warp][kk];              // smem broadcast
        const float kc = sk[warp][kk];
        qS.x = fmaf(qc, s.x, qS.x);  kS.x = fmaf(kc, s.x, kS.x);
        qS.y = fmaf(qc, s.y, qS.y);  kS.y = fmaf(kc, s.y, kS.y);
        qS.z = fmaf(qc, s.z, qS.z);  kS.z = fmaf(kc, s.z, kS.z);
        qS.w = fmaf(qc, s.w, qS.w);  kS.w = fmaf(kc, s.w, kS.w);
    }

    const float g  = gate[bh];
    const float bt = beta[bh];
    const float bq = qk * bt;
    const float4 vv = reinterpret_cast<const float4*>(v + (size_t)bh * DV)[lane];

    float4 o;
    o.x = fmaf(g, qS.x, bq * (vv.x - g * kS.x));
    o.y = fmaf(g, qS.y, bq * (vv.y - g * kS.y));
    o.z = fmaf(g, qS.z, bq * (vv.z - g * kS.z));
    o.w = fmaf(g, qS.w, bq * (vv.w - g * kS.w));
    reinterpret_cast<float4*>(out + (size_t)bh * DV)[lane] = o;
}

extern "C" void kernel_launch(void* const* d_in, const int* in_sizes, int n_in,
                              void* d_out, int out_size) {
    const float* q     = (const float*)d_in[0];
    const float* k     = (const float*)d_in[1];
    const float* v     = (const float*)d_in[2];
    const float* beta  = (const float*)d_in[3];
    const float* gate  = (const float*)d_in[4];
    const float* state = (const float*)d_in[5];
    float* out = (float*)d_out;

    const int BH = in_sizes[3];   // beta: B*H elements
    const int grid = (BH + WARPS_PER_CTA - 1) / WARPS_PER_CTA;

    deltanet_step_kernel<<<grid, WARPS_PER_CTA * 32>>>(q, k, v, beta, gate, state, out, BH);
}